// round 1
// baseline (speedup 1.0000x reference)
#include <cuda_runtime.h>
#include <math.h>

#define B_SIZE  4
#define T_SEQ   2048
#define D_MODEL 1024
#define N_HEADS 16
#define H_DIM   64
#define M_ROWS  (B_SIZE * T_SEQ)   // 8192

// Scratch (no cudaMalloc allowed): qkv = 8192 x 3072 f32, attn out = 8192 x 1024 f32
__device__ float g_qkv[(size_t)M_ROWS * 3 * D_MODEL];
__device__ float g_att[(size_t)M_ROWS * D_MODEL];

// ---------------------------------------------------------------------------
// Generic SGEMM with bias epilogue: C[M,N] = A[M,K] * B[K,N] + bias[N]
// BM=BN=128, BK=8, TM=TN=8, 256 threads. Requires M%128==0, N%128==0, K%8==0.
// ---------------------------------------------------------------------------
template<int BM, int BN, int BK, int TM, int TN>
__global__ void __launch_bounds__((BM / TM) * (BN / TN))
sgemm_bias_kernel(int M, int N, int K,
                  const float* __restrict__ A,
                  const float* __restrict__ Bm,
                  const float* __restrict__ bias,
                  float* __restrict__ C)
{
    __shared__ float As[BK][BM];   // A tile stored transposed
    __shared__ float Bs[BK][BN];

    const int tid  = threadIdx.x;
    const int cRow = blockIdx.y;
    const int cCol = blockIdx.x;

    A  += (size_t)cRow * BM * K;
    Bm += (size_t)cCol * BN;
    C  += (size_t)cRow * BM * N + (size_t)cCol * BN;
    const float* biasp = bias + (size_t)cCol * BN;

    const int iRA = tid / (BK / 4);          // 0..127
    const int iCA = (tid % (BK / 4)) * 4;    // 0 or 4
    const int iRB = tid / (BN / 4);          // 0..7
    const int iCB = (tid % (BN / 4)) * 4;    // 0..124

    const int tr = tid / (BN / TN);          // 0..15
    const int tc = tid % (BN / TN);          // 0..15

    float acc[TM][TN];
#pragma unroll
    for (int i = 0; i < TM; ++i)
#pragma unroll
        for (int j = 0; j < TN; ++j) acc[i][j] = 0.0f;

    for (int k0 = 0; k0 < K; k0 += BK) {
        float4 a4 = *(const float4*)(A + (size_t)iRA * K + iCA);
        As[iCA + 0][iRA] = a4.x;
        As[iCA + 1][iRA] = a4.y;
        As[iCA + 2][iRA] = a4.z;
        As[iCA + 3][iRA] = a4.w;
        *(float4*)(&Bs[iRB][iCB]) = *(const float4*)(Bm + (size_t)iRB * N + iCB);
        __syncthreads();

        A  += BK;
        Bm += (size_t)BK * N;

#pragma unroll
        for (int kk = 0; kk < BK; ++kk) {
            float rM[TM], rN[TN];
            *(float4*)&rM[0] = *(const float4*)&As[kk][tr * TM];
            *(float4*)&rM[4] = *(const float4*)&As[kk][tr * TM + 4];
            *(float4*)&rN[0] = *(const float4*)&Bs[kk][tc * TN];
            *(float4*)&rN[4] = *(const float4*)&Bs[kk][tc * TN + 4];
#pragma unroll
            for (int i = 0; i < TM; ++i)
#pragma unroll
                for (int j = 0; j < TN; ++j)
                    acc[i][j] += rM[i] * rN[j];
        }
        __syncthreads();
    }

#pragma unroll
    for (int i = 0; i < TM; ++i) {
        float* crow = C + (size_t)(tr * TM + i) * N + tc * TN;
#pragma unroll
        for (int j = 0; j < TN; j += 4) {
            float4 bv = *(const float4*)(biasp + tc * TN + j);
            float4 o;
            o.x = acc[i][j + 0] + bv.x;
            o.y = acc[i][j + 1] + bv.y;
            o.z = acc[i][j + 2] + bv.z;
            o.w = acc[i][j + 3] + bv.w;
            *(float4*)(crow + j) = o;
        }
    }
}

// ---------------------------------------------------------------------------
// Flash attention, fp32, online softmax.
// One block per (b, h, q-tile of 64 rows). 256 threads, each owns a 4x4 micro-
// tile of the 64x64 S/P tile and of the 64x64 O tile.
// Reads Q/K/V directly from the fused qkv buffer: row stride 3*D_MODEL,
// head offset h*64, section offsets {0, D, 2D}.
// ---------------------------------------------------------------------------
#define ATT_BM  64
#define ATT_BN  64
#define ATT_LD  68      // padded row stride (floats) to dodge bank conflicts
#define ATT_SMEM_BYTES (4 * H_DIM * ATT_LD * (int)sizeof(float))  // 69632

__global__ void __launch_bounds__(256)
flash_attn_kernel(const float* __restrict__ qkv, float* __restrict__ out)
{
    extern __shared__ float smem[];
    float* sQ = smem;                    // sQ[d][i]  (Q transposed)
    float* sK = sQ + H_DIM * ATT_LD;     // sK[d][j]  (K transposed)
    float* sV = sK + H_DIM * ATT_LD;     // sV[j][d]
    float* sP = sV + ATT_BN * ATT_LD;    // sP[j][i]  (P transposed)

    const int tid = threadIdx.x;
    const int bh  = blockIdx.y;
    const int b   = bh >> 4;
    const int h   = bh & 15;
    const int q0  = blockIdx.x * ATT_BM;

    const float* qbase = qkv + ((size_t)b * T_SEQ) * (3 * D_MODEL) + h * H_DIM;
    const float* kbase = qbase + D_MODEL;
    const float* vbase = qbase + 2 * D_MODEL;

    const int tr = tid >> 4;   // 0..15 -> rows 4*tr .. 4*tr+3
    const int tc = tid & 15;   // 0..15 -> cols 4*tc .. 4*tc+3

    // Load Q tile transposed: sQ[d][i] = Q[q0+i][d]
#pragma unroll
    for (int it = 0; it < 4; ++it) {
        int idx = tid + it * 256;       // 0..1023 float4 chunks over 64x64
        int i   = idx >> 4;             // q row 0..63
        int d0  = (idx & 15) << 2;      // 0..60
        float4 v = *(const float4*)(qbase + (size_t)(q0 + i) * (3 * D_MODEL) + d0);
        sQ[(d0 + 0) * ATT_LD + i] = v.x;
        sQ[(d0 + 1) * ATT_LD + i] = v.y;
        sQ[(d0 + 2) * ATT_LD + i] = v.z;
        sQ[(d0 + 3) * ATT_LD + i] = v.w;
    }

    float m[4], l[4], accO[4][4];
#pragma unroll
    for (int i = 0; i < 4; ++i) {
        m[i] = -INFINITY;
        l[i] = 0.0f;
#pragma unroll
        for (int j = 0; j < 4; ++j) accO[i][j] = 0.0f;
    }

    const float scale = 0.125f;  // 1/sqrt(64)

    for (int kt = 0; kt < T_SEQ / ATT_BN; ++kt) {
        const int k0 = kt * ATT_BN;
        __syncthreads();   // protect sK/sV/sP from previous iteration's readers

        // Load K transposed + V natural
#pragma unroll
        for (int it = 0; it < 4; ++it) {
            int idx = tid + it * 256;
            int j   = idx >> 4;
            int d0  = (idx & 15) << 2;
            float4 kv4 = *(const float4*)(kbase + (size_t)(k0 + j) * (3 * D_MODEL) + d0);
            sK[(d0 + 0) * ATT_LD + j] = kv4.x;
            sK[(d0 + 1) * ATT_LD + j] = kv4.y;
            sK[(d0 + 2) * ATT_LD + j] = kv4.z;
            sK[(d0 + 3) * ATT_LD + j] = kv4.w;
            float4 vv4 = *(const float4*)(vbase + (size_t)(k0 + j) * (3 * D_MODEL) + d0);
            *(float4*)(&sV[j * ATT_LD + d0]) = vv4;
        }
        __syncthreads();

        // S = Q @ K^T (4x4 microtile per thread)
        float s[4][4];
#pragma unroll
        for (int i = 0; i < 4; ++i)
#pragma unroll
            for (int j = 0; j < 4; ++j) s[i][j] = 0.0f;

#pragma unroll 16
        for (int d = 0; d < H_DIM; ++d) {
            float4 q4 = *(const float4*)&sQ[d * ATT_LD + tr * 4];
            float4 k4 = *(const float4*)&sK[d * ATT_LD + tc * 4];
            float qa[4] = {q4.x, q4.y, q4.z, q4.w};
            float ka[4] = {k4.x, k4.y, k4.z, k4.w};
#pragma unroll
            for (int i = 0; i < 4; ++i)
#pragma unroll
                for (int j = 0; j < 4; ++j)
                    s[i][j] += qa[i] * ka[j];
        }

        // Online softmax (row groups of 16 threads: same tr, tc = 0..15)
#pragma unroll
        for (int i = 0; i < 4; ++i) {
#pragma unroll
            for (int j = 0; j < 4; ++j) s[i][j] *= scale;

            float rm = fmaxf(fmaxf(s[i][0], s[i][1]), fmaxf(s[i][2], s[i][3]));
            rm = fmaxf(rm, __shfl_xor_sync(0xffffffffu, rm, 1));
            rm = fmaxf(rm, __shfl_xor_sync(0xffffffffu, rm, 2));
            rm = fmaxf(rm, __shfl_xor_sync(0xffffffffu, rm, 4));
            rm = fmaxf(rm, __shfl_xor_sync(0xffffffffu, rm, 8));

            float mn    = fmaxf(m[i], rm);
            float alpha = __expf(m[i] - mn);
            m[i] = mn;

            float rs = 0.0f;
#pragma unroll
            for (int j = 0; j < 4; ++j) {
                s[i][j] = __expf(s[i][j] - mn);
                rs += s[i][j];
            }
            rs += __shfl_xor_sync(0xffffffffu, rs, 1);
            rs += __shfl_xor_sync(0xffffffffu, rs, 2);
            rs += __shfl_xor_sync(0xffffffffu, rs, 4);
            rs += __shfl_xor_sync(0xffffffffu, rs, 8);

            l[i] = l[i] * alpha + rs;
#pragma unroll
            for (int j = 0; j < 4; ++j) accO[i][j] *= alpha;
        }

        // Stage P transposed: sP[kv][q]
#pragma unroll
        for (int i = 0; i < 4; ++i)
#pragma unroll
            for (int j = 0; j < 4; ++j)
                sP[(tc * 4 + j) * ATT_LD + (tr * 4 + i)] = s[i][j];
        __syncthreads();

        // O += P @ V
#pragma unroll 16
        for (int kk = 0; kk < ATT_BN; ++kk) {
            float4 p4 = *(const float4*)&sP[kk * ATT_LD + tr * 4];
            float4 v4 = *(const float4*)&sV[kk * ATT_LD + tc * 4];
            float pa[4] = {p4.x, p4.y, p4.z, p4.w};
            float va[4] = {v4.x, v4.y, v4.z, v4.w};
#pragma unroll
            for (int i = 0; i < 4; ++i)
#pragma unroll
                for (int j = 0; j < 4; ++j)
                    accO[i][j] += pa[i] * va[j];
        }
    }

    // Normalize + write out[(b*T + q0 + row)][h*64 + col]
#pragma unroll
    for (int i = 0; i < 4; ++i) {
        float inv = 1.0f / l[i];
        size_t row = (size_t)b * T_SEQ + q0 + tr * 4 + i;
        float4 o;
        o.x = accO[i][0] * inv;
        o.y = accO[i][1] * inv;
        o.z = accO[i][2] * inv;
        o.w = accO[i][3] * inv;
        *(float4*)(out + row * D_MODEL + h * H_DIM + tc * 4) = o;
    }
}

// ---------------------------------------------------------------------------
extern "C" void kernel_launch(void* const* d_in, const int* in_sizes, int n_in,
                              void* d_out, int out_size)
{
    const float* x     = (const float*)d_in[0];
    const float* W_qkv = (const float*)d_in[1];
    const float* b_qkv = (const float*)d_in[2];
    const float* W_out = (const float*)d_in[3];
    const float* b_out = (const float*)d_in[4];
    float*       out   = (float*)d_out;

    float *qkv_ptr, *att_ptr;
    cudaGetSymbolAddress((void**)&qkv_ptr, g_qkv);
    cudaGetSymbolAddress((void**)&att_ptr, g_att);

    // 1) QKV projection: [8192,1024] x [1024,3072] + bias
    {
        dim3 grid((3 * D_MODEL) / 128, M_ROWS / 128);
        sgemm_bias_kernel<128, 128, 8, 8, 8><<<grid, 256>>>(
            M_ROWS, 3 * D_MODEL, D_MODEL, x, W_qkv, b_qkv, qkv_ptr);
    }

    // 2) Attention
    {
        cudaFuncSetAttribute(flash_attn_kernel,
                             cudaFuncAttributeMaxDynamicSharedMemorySize,
                             ATT_SMEM_BYTES);
        dim3 grid(T_SEQ / ATT_BM, B_SIZE * N_HEADS);
        flash_attn_kernel<<<grid, 256, ATT_SMEM_BYTES>>>(qkv_ptr, att_ptr);
    }

    // 3) Output projection: [8192,1024] x [1024,1024] + bias
    {
        dim3 grid(D_MODEL / 128, M_ROWS / 128);
        sgemm_bias_kernel<128, 128, 8, 8, 8><<<grid, 256>>>(
            M_ROWS, D_MODEL, D_MODEL, att_ptr, W_out, b_out, out);
    }
}

// round 5
// speedup vs baseline: 2.8951x; 2.8951x over previous
#include <cuda_runtime.h>
#include <math.h>
#include <stdint.h>

#define B_SIZE  4
#define T_SEQ   2048
#define D_MODEL 1024
#define N_HEADS 16
#define H_DIM   64
#define M_ROWS  (B_SIZE * T_SEQ)   // 8192

// Scratch (no cudaMalloc allowed)
__device__ float g_qkv[(size_t)M_ROWS * 3 * D_MODEL];
__device__ float g_att[(size_t)M_ROWS * D_MODEL];

__device__ __forceinline__ uint32_t f2tf32(float f) {
    uint32_t r;
    asm("cvt.rna.tf32.f32 %0, %1;" : "=r"(r) : "f"(f));
    return r;
}

// mma.sync m16n8k8 tf32 (A row-major, B col-major, fp32 accum) — baseline PTX,
// no sm_103a-only features required.
#define MMA_TF32(c, a, b)                                                     \
    asm volatile("mma.sync.aligned.m16n8k8.row.col.f32.tf32.tf32.f32 "        \
        "{%0,%1,%2,%3}, {%4,%5,%6,%7}, {%8,%9}, {%0,%1,%2,%3};"               \
        : "+f"((c)[0]), "+f"((c)[1]), "+f"((c)[2]), "+f"((c)[3])              \
        : "r"((a)[0]), "r"((a)[1]), "r"((a)[2]), "r"((a)[3]),                 \
          "r"((b)[0]), "r"((b)[1]))

// ---------------------------------------------------------------------------
// TF32 tensor-core GEMM: C[M,N] = A[M,K] * B[K,N] + bias[N]
// 128x128 block tile, BK=32 double-buffered, 256 threads (8 warps, 2x4),
// warp tile 64x32 (4 m-tiles x 4 n-tiles of m16n8k8).
// ---------------------------------------------------------------------------
#define GT   256
#define GBM  128
#define GBN  128
#define GBK  32
#define LDA_S 36    // padded row stride (words) for A tile: banks 4q+c unique
#define LDB_S 132   // padded row stride for B tile: banks 4c+q unique
#define GA_WORDS (GBM * LDA_S)       // 4608
#define GB_WORDS (GBK * LDB_S)       // 4224
#define G_SMEM_BYTES (2 * (GA_WORDS + GB_WORDS) * 4)   // 70656

__global__ void __launch_bounds__(GT)
gemm_tf32_mma(int M, int N, int K,
              const float* __restrict__ A,
              const float* __restrict__ Bm,
              const float* __restrict__ bias,
              float* __restrict__ C)
{
    extern __shared__ uint32_t gsm[];
    uint32_t* sA = gsm;                 // [2][GA_WORDS]
    uint32_t* sB = gsm + 2 * GA_WORDS;  // [2][GB_WORDS]

    const int tid  = threadIdx.x;
    const int wid  = tid >> 5;
    const int lane = tid & 31;
    const int lq   = lane >> 2;   // 0..7
    const int lr   = lane & 3;    // 0..3
    const int wm   = wid & 1;     // warp row (x64)
    const int wn   = wid >> 1;    // warp col (x32)

    const size_t row0 = (size_t)blockIdx.y * GBM;
    const size_t col0 = (size_t)blockIdx.x * GBN;
    const int NC = K / GBK;

    float acc[4][4][4];
#pragma unroll
    for (int mi = 0; mi < 4; ++mi)
#pragma unroll
        for (int ni = 0; ni < 4; ++ni)
#pragma unroll
            for (int j = 0; j < 4; ++j) acc[mi][ni][j] = 0.0f;

    float4 areg[4], breg[4];

    auto load_regs = [&](int kc) {
#pragma unroll
        for (int it = 0; it < 4; ++it) {
            int idx = tid + it * GT;
            int ra  = idx >> 3;            // 0..127
            int ca  = (idx & 7) << 2;      // 0..28
            areg[it] = *(const float4*)(A + (row0 + ra) * K + kc * GBK + ca);
            int rb  = idx >> 5;            // 0..31
            int cb  = (idx & 31) << 2;     // 0..124
            breg[it] = *(const float4*)(Bm + (size_t)(kc * GBK + rb) * N + col0 + cb);
        }
    };
    auto store_smem = [&](int buf) {
        uint32_t* dA = sA + buf * GA_WORDS;
        uint32_t* dB = sB + buf * GB_WORDS;
#pragma unroll
        for (int it = 0; it < 4; ++it) {
            int idx = tid + it * GT;
            int ra  = idx >> 3;
            int ca  = (idx & 7) << 2;
            uint4 ta = { f2tf32(areg[it].x), f2tf32(areg[it].y),
                         f2tf32(areg[it].z), f2tf32(areg[it].w) };
            *(uint4*)(dA + ra * LDA_S + ca) = ta;
            int rb  = idx >> 5;
            int cb  = (idx & 31) << 2;
            uint4 tb = { f2tf32(breg[it].x), f2tf32(breg[it].y),
                         f2tf32(breg[it].z), f2tf32(breg[it].w) };
            *(uint4*)(dB + rb * LDB_S + cb) = tb;
        }
    };

    load_regs(0);
    store_smem(0);
    __syncthreads();

    for (int kc = 0; kc < NC; ++kc) {
        if (kc + 1 < NC) load_regs(kc + 1);

        const uint32_t* As = sA + (kc & 1) * GA_WORDS;
        const uint32_t* Bs = sB + (kc & 1) * GB_WORDS;
#pragma unroll
        for (int kk = 0; kk < 4; ++kk) {
            uint32_t a[4][4], b[4][2];
#pragma unroll
            for (int mi = 0; mi < 4; ++mi) {
                int r = wm * 64 + mi * 16 + lq;
                a[mi][0] = As[r * LDA_S + kk * 8 + lr];
                a[mi][1] = As[(r + 8) * LDA_S + kk * 8 + lr];
                a[mi][2] = As[r * LDA_S + kk * 8 + lr + 4];
                a[mi][3] = As[(r + 8) * LDA_S + kk * 8 + lr + 4];
            }
#pragma unroll
            for (int ni = 0; ni < 4; ++ni) {
                int cn = wn * 32 + ni * 8 + lq;
                b[ni][0] = Bs[(kk * 8 + lr) * LDB_S + cn];
                b[ni][1] = Bs[(kk * 8 + lr + 4) * LDB_S + cn];
            }
#pragma unroll
            for (int mi = 0; mi < 4; ++mi)
#pragma unroll
                for (int ni = 0; ni < 4; ++ni)
                    MMA_TF32(acc[mi][ni], a[mi], b[ni]);
        }

        if (kc + 1 < NC) store_smem((kc + 1) & 1);
        __syncthreads();
    }

    // Epilogue: direct fragment stores + bias
#pragma unroll
    for (int mi = 0; mi < 4; ++mi) {
#pragma unroll
        for (int ni = 0; ni < 4; ++ni) {
            size_t r  = row0 + wm * 64 + mi * 16 + lq;
            size_t cn = col0 + wn * 32 + ni * 8 + 2 * lr;
            float2 bv = *(const float2*)(bias + cn);
            float2 o0 = { acc[mi][ni][0] + bv.x, acc[mi][ni][1] + bv.y };
            float2 o1 = { acc[mi][ni][2] + bv.x, acc[mi][ni][3] + bv.y };
            *(float2*)(C + r * N + cn)       = o0;
            *(float2*)(C + (r + 8) * N + cn) = o1;
        }
    }
}

// ---------------------------------------------------------------------------
// Flash attention with mma.sync tf32.
// Block: 128 q-rows x (one b,h). 256 threads = 8 warps; warp w owns q rows
// [w*16, w*16+16). KV tiles of 64. S/P tiles 128x64, O accum 128x64.
// ---------------------------------------------------------------------------
#define AQ   128
#define AKV  64
#define LDQ  68
#define LDK  68
#define LDV  72
#define LDP  68
#define ATT_SMEM_WORDS (AQ * LDQ + AKV * LDK + AKV * LDV + AQ * LDP)
#define ATT_SMEM_BYTES (ATT_SMEM_WORDS * 4)    // 105472

__global__ void __launch_bounds__(256)
flash_attn_mma(const float* __restrict__ qkv, float* __restrict__ out)
{
    extern __shared__ uint32_t asm_[];
    uint32_t* sQ = asm_;                     // [AQ][LDQ]  tf32 Q
    uint32_t* sK = sQ + AQ * LDQ;            // [AKV][LDK] tf32 K
    uint32_t* sV = sK + AKV * LDK;           // [AKV][LDV] tf32 V
    uint32_t* sP = sV + AKV * LDV;           // [AQ][LDP]  tf32 P

    const int tid  = threadIdx.x;
    const int wid  = tid >> 5;
    const int lane = tid & 31;
    const int lq   = lane >> 2;
    const int lr   = lane & 3;

    const int bh = blockIdx.y;
    const int b  = bh >> 4;
    const int h  = bh & 15;
    const int q0 = blockIdx.x * AQ;

    const float* qbase = qkv + ((size_t)b * T_SEQ) * (3 * D_MODEL) + h * H_DIM;
    const float* kbase = qbase + D_MODEL;
    const float* vbase = qbase + 2 * D_MODEL;

    // Load Q tile (128 x 64) once, convert to tf32
#pragma unroll
    for (int it = 0; it < 8; ++it) {
        int idx = tid + it * 256;          // 0..2047 float4 slots
        int row = idx >> 4;                // 0..127
        int c4  = (idx & 15) << 2;         // 0..60
        float4 v = *(const float4*)(qbase + (size_t)(q0 + row) * (3 * D_MODEL) + c4);
        uint4 t = { f2tf32(v.x), f2tf32(v.y), f2tf32(v.z), f2tf32(v.w) };
        *(uint4*)(sQ + row * LDQ + c4) = t;
    }

    float o[8][4];
    float m0 = -INFINITY, m1 = -INFINITY, l0 = 0.0f, l1 = 0.0f;
#pragma unroll
    for (int ni = 0; ni < 8; ++ni)
#pragma unroll
        for (int j = 0; j < 4; ++j) o[ni][j] = 0.0f;

    const float scale = 0.125f;  // 1/sqrt(64)
    const int qr = wid * 16 + lq;   // this thread's first local q row

    for (int kt = 0; kt < T_SEQ / AKV; ++kt) {
        const int k0 = kt * AKV;
        __syncthreads();   // previous iteration's consumers of sK/sV done

        // Load K & V tiles (64 x 64 each), convert to tf32
#pragma unroll
        for (int it = 0; it < 4; ++it) {
            int idx = tid + it * 256;      // 0..1023
            int row = idx >> 4;            // 0..63
            int c4  = (idx & 15) << 2;     // 0..60
            float4 kv4 = *(const float4*)(kbase + (size_t)(k0 + row) * (3 * D_MODEL) + c4);
            uint4 tk = { f2tf32(kv4.x), f2tf32(kv4.y), f2tf32(kv4.z), f2tf32(kv4.w) };
            *(uint4*)(sK + row * LDK + c4) = tk;
            float4 vv4 = *(const float4*)(vbase + (size_t)(k0 + row) * (3 * D_MODEL) + c4);
            uint4 tv = { f2tf32(vv4.x), f2tf32(vv4.y), f2tf32(vv4.z), f2tf32(vv4.w) };
            *(uint4*)(sV + row * LDV + c4) = tv;
        }
        __syncthreads();

        // S = Q @ K^T : per warp 16x64, 8 k-steps over d
        float s[8][4];
#pragma unroll
        for (int ni = 0; ni < 8; ++ni)
#pragma unroll
            for (int j = 0; j < 4; ++j) s[ni][j] = 0.0f;

#pragma unroll
        for (int kk = 0; kk < 8; ++kk) {
            uint32_t a[4];
            a[0] = sQ[qr * LDQ + kk * 8 + lr];
            a[1] = sQ[(qr + 8) * LDQ + kk * 8 + lr];
            a[2] = sQ[qr * LDQ + kk * 8 + lr + 4];
            a[3] = sQ[(qr + 8) * LDQ + kk * 8 + lr + 4];
#pragma unroll
            for (int ni = 0; ni < 8; ++ni) {
                uint32_t bfr[2];
                bfr[0] = sK[(ni * 8 + lq) * LDK + kk * 8 + lr];
                bfr[1] = sK[(ni * 8 + lq) * LDK + kk * 8 + lr + 4];
                MMA_TF32(s[ni], a, bfr);
            }
        }

        // Online softmax: thread owns rows (qr) via regs {0,1} and (qr+8) via {2,3}
        float rm0 = -INFINITY, rm1 = -INFINITY;
#pragma unroll
        for (int ni = 0; ni < 8; ++ni) {
#pragma unroll
            for (int j = 0; j < 4; ++j) s[ni][j] *= scale;
            rm0 = fmaxf(rm0, fmaxf(s[ni][0], s[ni][1]));
            rm1 = fmaxf(rm1, fmaxf(s[ni][2], s[ni][3]));
        }
        rm0 = fmaxf(rm0, __shfl_xor_sync(0xffffffffu, rm0, 1));
        rm0 = fmaxf(rm0, __shfl_xor_sync(0xffffffffu, rm0, 2));
        rm1 = fmaxf(rm1, __shfl_xor_sync(0xffffffffu, rm1, 1));
        rm1 = fmaxf(rm1, __shfl_xor_sync(0xffffffffu, rm1, 2));

        float mn0 = fmaxf(m0, rm0), mn1 = fmaxf(m1, rm1);
        float al0 = __expf(m0 - mn0), al1 = __expf(m1 - mn1);
        m0 = mn0; m1 = mn1;

        float rs0 = 0.0f, rs1 = 0.0f;
#pragma unroll
        for (int ni = 0; ni < 8; ++ni) {
            s[ni][0] = __expf(s[ni][0] - mn0);
            s[ni][1] = __expf(s[ni][1] - mn0);
            s[ni][2] = __expf(s[ni][2] - mn1);
            s[ni][3] = __expf(s[ni][3] - mn1);
            rs0 += s[ni][0] + s[ni][1];
            rs1 += s[ni][2] + s[ni][3];
        }
        rs0 += __shfl_xor_sync(0xffffffffu, rs0, 1);
        rs0 += __shfl_xor_sync(0xffffffffu, rs0, 2);
        rs1 += __shfl_xor_sync(0xffffffffu, rs1, 1);
        rs1 += __shfl_xor_sync(0xffffffffu, rs1, 2);

        l0 = l0 * al0 + rs0;
        l1 = l1 * al1 + rs1;
#pragma unroll
        for (int ni = 0; ni < 8; ++ni) {
            o[ni][0] *= al0; o[ni][1] *= al0;
            o[ni][2] *= al1; o[ni][3] *= al1;
        }

        // Stage P (own 16 rows) to smem as tf32 for the A-fragment reload
#pragma unroll
        for (int ni = 0; ni < 8; ++ni) {
            int cn = ni * 8 + 2 * lr;
            sP[qr * LDP + cn]           = f2tf32(s[ni][0]);
            sP[qr * LDP + cn + 1]       = f2tf32(s[ni][1]);
            sP[(qr + 8) * LDP + cn]     = f2tf32(s[ni][2]);
            sP[(qr + 8) * LDP + cn + 1] = f2tf32(s[ni][3]);
        }
        __syncwarp();

        // O += P @ V : k-dim = kv (64), n-dim = d (64)
#pragma unroll
        for (int kk = 0; kk < 8; ++kk) {
            uint32_t a[4];
            a[0] = sP[qr * LDP + kk * 8 + lr];
            a[1] = sP[(qr + 8) * LDP + kk * 8 + lr];
            a[2] = sP[qr * LDP + kk * 8 + lr + 4];
            a[3] = sP[(qr + 8) * LDP + kk * 8 + lr + 4];
#pragma unroll
            for (int ni = 0; ni < 8; ++ni) {
                uint32_t bfr[2];
                bfr[0] = sV[(kk * 8 + lr) * LDV + ni * 8 + lq];
                bfr[1] = sV[(kk * 8 + lr + 4) * LDV + ni * 8 + lq];
                MMA_TF32(o[ni], a, bfr);
            }
        }
    }

    // Normalize + write out[(b*T + q0 + row)][h*64 + col]
    float inv0 = 1.0f / l0, inv1 = 1.0f / l1;
    size_t row_g = (size_t)b * T_SEQ + q0 + qr;
#pragma unroll
    for (int ni = 0; ni < 8; ++ni) {
        int cn = h * H_DIM + ni * 8 + 2 * lr;
        float2 o0 = { o[ni][0] * inv0, o[ni][1] * inv0 };
        float2 o1 = { o[ni][2] * inv1, o[ni][3] * inv1 };
        *(float2*)(out + row_g * D_MODEL + cn)       = o0;
        *(float2*)(out + (row_g + 8) * D_MODEL + cn) = o1;
    }
}

// ---------------------------------------------------------------------------
extern "C" void kernel_launch(void* const* d_in, const int* in_sizes, int n_in,
                              void* d_out, int out_size)
{
    const float* x     = (const float*)d_in[0];
    const float* W_qkv = (const float*)d_in[1];
    const float* b_qkv = (const float*)d_in[2];
    const float* W_out = (const float*)d_in[3];
    const float* b_out = (const float*)d_in[4];
    float*       out   = (float*)d_out;

    float *qkv_ptr, *att_ptr;
    cudaGetSymbolAddress((void**)&qkv_ptr, g_qkv);
    cudaGetSymbolAddress((void**)&att_ptr, g_att);

    cudaFuncSetAttribute(gemm_tf32_mma,
                         cudaFuncAttributeMaxDynamicSharedMemorySize, G_SMEM_BYTES);
    cudaFuncSetAttribute(flash_attn_mma,
                         cudaFuncAttributeMaxDynamicSharedMemorySize, ATT_SMEM_BYTES);

    // 1) QKV projection: [8192,1024] x [1024,3072] + bias   (W used as [K,N])
    {
        dim3 grid((3 * D_MODEL) / GBN, M_ROWS / GBM);
        gemm_tf32_mma<<<grid, GT, G_SMEM_BYTES>>>(
            M_ROWS, 3 * D_MODEL, D_MODEL, x, W_qkv, b_qkv, qkv_ptr);
    }

    // 2) Attention
    {
        dim3 grid(T_SEQ / AQ, B_SIZE * N_HEADS);
        flash_attn_mma<<<grid, 256, ATT_SMEM_BYTES>>>(qkv_ptr, att_ptr);
    }

    // 3) Output projection: [8192,1024] x [1024,1024] + bias
    {
        dim3 grid(D_MODEL / GBN, M_ROWS / GBM);
        gemm_tf32_mma<<<grid, GT, G_SMEM_BYTES>>>(
            M_ROWS, D_MODEL, D_MODEL, att_ptr, W_out, b_out, out);
    }
}

// round 6
// speedup vs baseline: 3.3397x; 1.1535x over previous
#include <cuda_runtime.h>
#include <math.h>
#include <stdint.h>

#define B_SIZE  4
#define T_SEQ   2048
#define D_MODEL 1024
#define N_HEADS 16
#define H_DIM   64
#define M_ROWS  (B_SIZE * T_SEQ)   // 8192

// Scratch (no cudaMalloc allowed)
__device__ float g_qkv[(size_t)M_ROWS * 3 * D_MODEL];
__device__ float g_att[(size_t)M_ROWS * D_MODEL];

__device__ __forceinline__ uint32_t f2tf32(float f) {
    uint32_t r;
    asm("cvt.rna.tf32.f32 %0, %1;" : "=r"(r) : "f"(f));
    return r;
}
__device__ __forceinline__ uint32_t smem_u32(const void* p) {
    uint32_t a;
    asm("{ .reg .u64 t; cvta.to.shared.u64 t, %1; cvt.u32.u64 %0, t; }" : "=r"(a) : "l"(p));
    return a;
}

// mma.sync m16n8k8 tf32 (A row-major, B col-major, fp32 accum) — baseline PTX.
#define MMA_TF32(c, a, b)                                                     \
    asm volatile("mma.sync.aligned.m16n8k8.row.col.f32.tf32.tf32.f32 "        \
        "{%0,%1,%2,%3}, {%4,%5,%6,%7}, {%8,%9}, {%0,%1,%2,%3};"               \
        : "+f"((c)[0]), "+f"((c)[1]), "+f"((c)[2]), "+f"((c)[3])              \
        : "r"((a)[0]), "r"((a)[1]), "r"((a)[2]), "r"((a)[3]),                 \
          "r"((b)[0]), "r"((b)[1]))

#define CP_ASYNC16(dst, src) \
    asm volatile("cp.async.cg.shared.global [%0], [%1], 16;" :: "r"(dst), "l"(src))
#define CP_COMMIT() asm volatile("cp.async.commit_group;")
#define CP_WAIT(n)  asm volatile("cp.async.wait_group %0;" :: "n"(n))

// ---------------------------------------------------------------------------
// TF32 tensor-core GEMM: C[M,N] = A[M,K] * B[K,N] + bias[N]
// 128x128 block tile, BK=32 double-buffered via cp.async, 256 threads
// (8 warps 2x4), warp tile 64x32 (4x4 m16n8k8). 2 CTAs/SM.
// ---------------------------------------------------------------------------
#define GT   256
#define GBM  128
#define GBN  128
#define GBK  32
#define LDA_S 36    // padded row stride (words); 144B rows -> 16B aligned
#define LDB_S 132   // 528B rows -> 16B aligned
#define GA_WORDS (GBM * LDA_S)       // 4608
#define GB_WORDS (GBK * LDB_S)       // 4224
#define G_SMEM_BYTES (2 * (GA_WORDS + GB_WORDS) * 4)   // 70656

__global__ void __launch_bounds__(GT, 2)
gemm_tf32_mma(int M, int N, int K,
              const float* __restrict__ A,
              const float* __restrict__ Bm,
              const float* __restrict__ bias,
              float* __restrict__ C)
{
    extern __shared__ float gsm[];
    float* sA = gsm;                 // [2][GA_WORDS] raw fp32
    float* sB = gsm + 2 * GA_WORDS;  // [2][GB_WORDS]
    const uint32_t sA_u = smem_u32(sA);
    const uint32_t sB_u = smem_u32(sB);

    const int tid  = threadIdx.x;
    const int wid  = tid >> 5;
    const int lane = tid & 31;
    const int lq   = lane >> 2;   // 0..7
    const int lr   = lane & 3;    // 0..3
    const int wm   = wid & 1;     // warp row (x64)
    const int wn   = wid >> 1;    // warp col (x32)

    const size_t row0 = (size_t)blockIdx.y * GBM;
    const size_t col0 = (size_t)blockIdx.x * GBN;
    const int NC = K / GBK;

    // Per-thread fixed load coordinates
    const int ra = tid >> 3;             // 0..31 (x4 rows via it)
    const int ca = (tid & 7) << 2;       // 0..28
    const int rb = tid >> 5;             // 0..7  (x4 rows via it)
    const int cb = (tid & 31) << 2;      // 0..124

    auto issue = [&](int kc, int buf) {
        const float* Ag = A + row0 * K + (size_t)kc * GBK;
        const float* Bg = Bm + (size_t)kc * GBK * N + col0;
        uint32_t dA = sA_u + (uint32_t)(buf * GA_WORDS) * 4;
        uint32_t dB = sB_u + (uint32_t)(buf * GB_WORDS) * 4;
#pragma unroll
        for (int it = 0; it < 4; ++it) {
            int r  = ra + it * 32;
            CP_ASYNC16(dA + (uint32_t)(r * LDA_S + ca) * 4, Ag + (size_t)r * K + ca);
            int r2 = rb + it * 8;
            CP_ASYNC16(dB + (uint32_t)(r2 * LDB_S + cb) * 4, Bg + (size_t)r2 * N + cb);
        }
        CP_COMMIT();
    };

    float acc[4][4][4];
#pragma unroll
    for (int mi = 0; mi < 4; ++mi)
#pragma unroll
        for (int ni = 0; ni < 4; ++ni)
#pragma unroll
            for (int j = 0; j < 4; ++j) acc[mi][ni][j] = 0.0f;

    issue(0, 0);

    for (int kc = 0; kc < NC; ++kc) {
        if (kc + 1 < NC) { issue(kc + 1, (kc + 1) & 1); CP_WAIT(1); }
        else             { CP_WAIT(0); }
        __syncthreads();

        const float* As = sA + (kc & 1) * GA_WORDS;
        const float* Bs = sB + (kc & 1) * GB_WORDS;
#pragma unroll
        for (int kk = 0; kk < 4; ++kk) {
            uint32_t a[4][4], b[4][2];
#pragma unroll
            for (int mi = 0; mi < 4; ++mi) {
                int r = wm * 64 + mi * 16 + lq;
                a[mi][0] = f2tf32(As[r * LDA_S + kk * 8 + lr]);
                a[mi][1] = f2tf32(As[(r + 8) * LDA_S + kk * 8 + lr]);
                a[mi][2] = f2tf32(As[r * LDA_S + kk * 8 + lr + 4]);
                a[mi][3] = f2tf32(As[(r + 8) * LDA_S + kk * 8 + lr + 4]);
            }
#pragma unroll
            for (int ni = 0; ni < 4; ++ni) {
                int cn = wn * 32 + ni * 8 + lq;
                b[ni][0] = f2tf32(Bs[(kk * 8 + lr) * LDB_S + cn]);
                b[ni][1] = f2tf32(Bs[(kk * 8 + lr + 4) * LDB_S + cn]);
            }
#pragma unroll
            for (int mi = 0; mi < 4; ++mi)
#pragma unroll
                for (int ni = 0; ni < 4; ++ni)
                    MMA_TF32(acc[mi][ni], a[mi], b[ni]);
        }
        __syncthreads();
    }

    // Epilogue: direct fragment stores + bias
#pragma unroll
    for (int mi = 0; mi < 4; ++mi) {
#pragma unroll
        for (int ni = 0; ni < 4; ++ni) {
            size_t r  = row0 + wm * 64 + mi * 16 + lq;
            size_t cn = col0 + wn * 32 + ni * 8 + 2 * lr;
            float2 bv = *(const float2*)(bias + cn);
            float2 o0 = { acc[mi][ni][0] + bv.x, acc[mi][ni][1] + bv.y };
            float2 o1 = { acc[mi][ni][2] + bv.x, acc[mi][ni][3] + bv.y };
            *(float2*)(C + r * N + cn)       = o0;
            *(float2*)(C + (r + 8) * N + cn) = o1;
        }
    }
}

// ---------------------------------------------------------------------------
// Flash attention with mma.sync tf32. 2 CTAs/SM for phase overlap.
// Block: 128 q-rows x (one b,h). 256 threads = 8 warps; warp w owns q rows
// [w*16, w*16+16). KV tiles of 64.
// ---------------------------------------------------------------------------
#define AQ   128
#define AKV  64
#define LDQ  68
#define LDK  68
#define LDV  72
#define LDP  68
#define ATT_SMEM_WORDS (AQ * LDQ + AKV * LDK + AKV * LDV + AQ * LDP)
#define ATT_SMEM_BYTES (ATT_SMEM_WORDS * 4)    // 105472

__global__ void __launch_bounds__(256, 2)
flash_attn_mma(const float* __restrict__ qkv, float* __restrict__ out)
{
    extern __shared__ uint32_t asm_[];
    uint32_t* sQ = asm_;                     // [AQ][LDQ]  tf32 Q
    uint32_t* sK = sQ + AQ * LDQ;            // [AKV][LDK] tf32 K
    uint32_t* sV = sK + AKV * LDK;           // [AKV][LDV] tf32 V
    uint32_t* sP = sV + AKV * LDV;           // [AQ][LDP]  tf32 P

    const int tid  = threadIdx.x;
    const int wid  = tid >> 5;
    const int lane = tid & 31;
    const int lq   = lane >> 2;
    const int lr   = lane & 3;

    const int bh = blockIdx.y;
    const int b  = bh >> 4;
    const int h  = bh & 15;
    const int q0 = blockIdx.x * AQ;

    const float* qbase = qkv + ((size_t)b * T_SEQ) * (3 * D_MODEL) + h * H_DIM;
    const float* kbase = qbase + D_MODEL;
    const float* vbase = qbase + 2 * D_MODEL;

    // Load Q tile (128 x 64) once, convert to tf32
#pragma unroll
    for (int it = 0; it < 8; ++it) {
        int idx = tid + it * 256;
        int row = idx >> 4;
        int c4  = (idx & 15) << 2;
        float4 v = *(const float4*)(qbase + (size_t)(q0 + row) * (3 * D_MODEL) + c4);
        uint4 t = { f2tf32(v.x), f2tf32(v.y), f2tf32(v.z), f2tf32(v.w) };
        *(uint4*)(sQ + row * LDQ + c4) = t;
    }

    float o[8][4];
    float m0 = -INFINITY, m1 = -INFINITY, l0 = 0.0f, l1 = 0.0f;
#pragma unroll
    for (int ni = 0; ni < 8; ++ni)
#pragma unroll
        for (int j = 0; j < 4; ++j) o[ni][j] = 0.0f;

    const float scale = 0.125f;
    const int qr = wid * 16 + lq;

    for (int kt = 0; kt < T_SEQ / AKV; ++kt) {
        const int k0 = kt * AKV;
        __syncthreads();

#pragma unroll
        for (int it = 0; it < 4; ++it) {
            int idx = tid + it * 256;
            int row = idx >> 4;
            int c4  = (idx & 15) << 2;
            float4 kv4 = *(const float4*)(kbase + (size_t)(k0 + row) * (3 * D_MODEL) + c4);
            uint4 tk = { f2tf32(kv4.x), f2tf32(kv4.y), f2tf32(kv4.z), f2tf32(kv4.w) };
            *(uint4*)(sK + row * LDK + c4) = tk;
            float4 vv4 = *(const float4*)(vbase + (size_t)(k0 + row) * (3 * D_MODEL) + c4);
            uint4 tv = { f2tf32(vv4.x), f2tf32(vv4.y), f2tf32(vv4.z), f2tf32(vv4.w) };
            *(uint4*)(sV + row * LDV + c4) = tv;
        }
        __syncthreads();

        // S = Q @ K^T
        float s[8][4];
#pragma unroll
        for (int ni = 0; ni < 8; ++ni)
#pragma unroll
            for (int j = 0; j < 4; ++j) s[ni][j] = 0.0f;

#pragma unroll
        for (int kk = 0; kk < 8; ++kk) {
            uint32_t a[4];
            a[0] = sQ[qr * LDQ + kk * 8 + lr];
            a[1] = sQ[(qr + 8) * LDQ + kk * 8 + lr];
            a[2] = sQ[qr * LDQ + kk * 8 + lr + 4];
            a[3] = sQ[(qr + 8) * LDQ + kk * 8 + lr + 4];
#pragma unroll
            for (int ni = 0; ni < 8; ++ni) {
                uint32_t bfr[2];
                bfr[0] = sK[(ni * 8 + lq) * LDK + kk * 8 + lr];
                bfr[1] = sK[(ni * 8 + lq) * LDK + kk * 8 + lr + 4];
                MMA_TF32(s[ni], a, bfr);
            }
        }

        // Online softmax
        float rm0 = -INFINITY, rm1 = -INFINITY;
#pragma unroll
        for (int ni = 0; ni < 8; ++ni) {
#pragma unroll
            for (int j = 0; j < 4; ++j) s[ni][j] *= scale;
            rm0 = fmaxf(rm0, fmaxf(s[ni][0], s[ni][1]));
            rm1 = fmaxf(rm1, fmaxf(s[ni][2], s[ni][3]));
        }
        rm0 = fmaxf(rm0, __shfl_xor_sync(0xffffffffu, rm0, 1));
        rm0 = fmaxf(rm0, __shfl_xor_sync(0xffffffffu, rm0, 2));
        rm1 = fmaxf(rm1, __shfl_xor_sync(0xffffffffu, rm1, 1));
        rm1 = fmaxf(rm1, __shfl_xor_sync(0xffffffffu, rm1, 2));

        float mn0 = fmaxf(m0, rm0), mn1 = fmaxf(m1, rm1);
        float al0 = __expf(m0 - mn0), al1 = __expf(m1 - mn1);
        m0 = mn0; m1 = mn1;

        float rs0 = 0.0f, rs1 = 0.0f;
#pragma unroll
        for (int ni = 0; ni < 8; ++ni) {
            s[ni][0] = __expf(s[ni][0] - mn0);
            s[ni][1] = __expf(s[ni][1] - mn0);
            s[ni][2] = __expf(s[ni][2] - mn1);
            s[ni][3] = __expf(s[ni][3] - mn1);
            rs0 += s[ni][0] + s[ni][1];
            rs1 += s[ni][2] + s[ni][3];
        }
        rs0 += __shfl_xor_sync(0xffffffffu, rs0, 1);
        rs0 += __shfl_xor_sync(0xffffffffu, rs0, 2);
        rs1 += __shfl_xor_sync(0xffffffffu, rs1, 1);
        rs1 += __shfl_xor_sync(0xffffffffu, rs1, 2);

        l0 = l0 * al0 + rs0;
        l1 = l1 * al1 + rs1;
#pragma unroll
        for (int ni = 0; ni < 8; ++ni) {
            o[ni][0] *= al0; o[ni][1] *= al0;
            o[ni][2] *= al1; o[ni][3] *= al1;
        }

        // Stage P rows (warp-private region)
#pragma unroll
        for (int ni = 0; ni < 8; ++ni) {
            int cn = ni * 8 + 2 * lr;
            sP[qr * LDP + cn]           = f2tf32(s[ni][0]);
            sP[qr * LDP + cn + 1]       = f2tf32(s[ni][1]);
            sP[(qr + 8) * LDP + cn]     = f2tf32(s[ni][2]);
            sP[(qr + 8) * LDP + cn + 1] = f2tf32(s[ni][3]);
        }
        __syncwarp();

        // O += P @ V
#pragma unroll
        for (int kk = 0; kk < 8; ++kk) {
            uint32_t a[4];
            a[0] = sP[qr * LDP + kk * 8 + lr];
            a[1] = sP[(qr + 8) * LDP + kk * 8 + lr];
            a[2] = sP[qr * LDP + kk * 8 + lr + 4];
            a[3] = sP[(qr + 8) * LDP + kk * 8 + lr + 4];
#pragma unroll
            for (int ni = 0; ni < 8; ++ni) {
                uint32_t bfr[2];
                bfr[0] = sV[(kk * 8 + lr) * LDV + ni * 8 + lq];
                bfr[1] = sV[(kk * 8 + lr + 4) * LDV + ni * 8 + lq];
                MMA_TF32(o[ni], a, bfr);
            }
        }
    }

    // Normalize + write
    float inv0 = 1.0f / l0, inv1 = 1.0f / l1;
    size_t row_g = (size_t)b * T_SEQ + q0 + qr;
#pragma unroll
    for (int ni = 0; ni < 8; ++ni) {
        int cn = h * H_DIM + ni * 8 + 2 * lr;
        float2 o0 = { o[ni][0] * inv0, o[ni][1] * inv0 };
        float2 o1 = { o[ni][2] * inv1, o[ni][3] * inv1 };
        *(float2*)(out + row_g * D_MODEL + cn)       = o0;
        *(float2*)(out + (row_g + 8) * D_MODEL + cn) = o1;
    }
}

// ---------------------------------------------------------------------------
extern "C" void kernel_launch(void* const* d_in, const int* in_sizes, int n_in,
                              void* d_out, int out_size)
{
    const float* x     = (const float*)d_in[0];
    const float* W_qkv = (const float*)d_in[1];
    const float* b_qkv = (const float*)d_in[2];
    const float* W_out = (const float*)d_in[3];
    const float* b_out = (const float*)d_in[4];
    float*       out   = (float*)d_out;

    float *qkv_ptr, *att_ptr;
    cudaGetSymbolAddress((void**)&qkv_ptr, g_qkv);
    cudaGetSymbolAddress((void**)&att_ptr, g_att);

    cudaFuncSetAttribute(gemm_tf32_mma,
                         cudaFuncAttributeMaxDynamicSharedMemorySize, G_SMEM_BYTES);
    cudaFuncSetAttribute(flash_attn_mma,
                         cudaFuncAttributeMaxDynamicSharedMemorySize, ATT_SMEM_BYTES);

    // 1) QKV projection: [8192,1024] x [1024,3072] + bias  (W used as [K,N])
    {
        dim3 grid((3 * D_MODEL) / GBN, M_ROWS / GBM);
        gemm_tf32_mma<<<grid, GT, G_SMEM_BYTES>>>(
            M_ROWS, 3 * D_MODEL, D_MODEL, x, W_qkv, b_qkv, qkv_ptr);
    }

    // 2) Attention
    {
        dim3 grid(T_SEQ / AQ, B_SIZE * N_HEADS);
        flash_attn_mma<<<grid, 256, ATT_SMEM_BYTES>>>(qkv_ptr, att_ptr);
    }

    // 3) Output projection: [8192,1024] x [1024,1024] + bias
    {
        dim3 grid(D_MODEL / GBN, M_ROWS / GBM);
        gemm_tf32_mma<<<grid, GT, G_SMEM_BYTES>>>(
            M_ROWS, D_MODEL, D_MODEL, att_ptr, W_out, b_out, out);
    }
}

// round 8
// speedup vs baseline: 7.5068x; 2.2478x over previous
#include <cuda_runtime.h>
#include <cuda_fp16.h>
#include <math.h>
#include <stdint.h>

#define B_SIZE  4
#define T_SEQ   2048
#define D_MODEL 1024
#define N_HEADS 16
#define H_DIM   64
#define M_ROWS  (B_SIZE * T_SEQ)   // 8192

// Scratch (no cudaMalloc allowed)
__device__ __half g_x_h[(size_t)M_ROWS * D_MODEL];
__device__ __half g_wqkv_t[(size_t)3 * D_MODEL * D_MODEL];  // [N=3072][K=1024]
__device__ __half g_wout_t[(size_t)D_MODEL * D_MODEL];      // [N=1024][K=1024]
__device__ __half g_qkv_h[(size_t)M_ROWS * 3 * D_MODEL];
__device__ __half g_att_h[(size_t)M_ROWS * D_MODEL];

__device__ __forceinline__ uint32_t smem_u32(const void* p) {
    uint32_t a;
    asm("{ .reg .u64 t; cvta.to.shared.u64 t, %1; cvt.u32.u64 %0, t; }" : "=r"(a) : "l"(p));
    return a;
}
__device__ __forceinline__ uint32_t packh2(float x, float y) {
    __half2 h = __floats2half2_rn(x, y);
    return *(uint32_t*)&h;
}

#define LDM_X4(r0, r1, r2, r3, addr)                                          \
    asm volatile("ldmatrix.sync.aligned.m8n8.x4.shared.b16 {%0,%1,%2,%3}, [%4];" \
        : "=r"(r0), "=r"(r1), "=r"(r2), "=r"(r3) : "r"(addr))
#define LDM_X4_T(r0, r1, r2, r3, addr)                                        \
    asm volatile("ldmatrix.sync.aligned.m8n8.x4.trans.shared.b16 {%0,%1,%2,%3}, [%4];" \
        : "=r"(r0), "=r"(r1), "=r"(r2), "=r"(r3) : "r"(addr))
#define MMA_F16(c, a, b)                                                      \
    asm volatile("mma.sync.aligned.m16n8k16.row.col.f32.f16.f16.f32 "         \
        "{%0,%1,%2,%3},{%4,%5,%6,%7},{%8,%9},{%0,%1,%2,%3};"                  \
        : "+f"((c)[0]), "+f"((c)[1]), "+f"((c)[2]), "+f"((c)[3])              \
        : "r"((a)[0]), "r"((a)[1]), "r"((a)[2]), "r"((a)[3]),                 \
          "r"((b)[0]), "r"((b)[1]))
#define CP_ASYNC16(dst, src) \
    asm volatile("cp.async.cg.shared.global [%0], [%1], 16;" :: "r"(dst), "l"(src))
#define CP_COMMIT() asm volatile("cp.async.commit_group;")
#define CP_WAIT1()  asm volatile("cp.async.wait_group 1;")
#define CP_WAIT0()  asm volatile("cp.async.wait_group 0;")

// ---------------------------------------------------------------------------
// Conversion pre-pass kernels
// ---------------------------------------------------------------------------
__global__ void conv_f16_kernel(const float* __restrict__ in, __half* __restrict__ outp, int n4)
{
    int i = blockIdx.x * blockDim.x + threadIdx.x;
    if (i >= n4) return;
    float4 v = ((const float4*)in)[i];
    __half2* o = (__half2*)outp + (size_t)i * 2;
    o[0] = __floats2half2_rn(v.x, v.y);
    o[1] = __floats2half2_rn(v.z, v.w);
}

// out[n][k] (f16) = in[k][n] (f32); R = rows(K) of in, C = cols(N) of in
__global__ void conv_transpose_f16(const float* __restrict__ in, __half* __restrict__ outp,
                                   int R, int C)
{
    __shared__ float t[32][33];
    int bx = blockIdx.x * 32, by = blockIdx.y * 32;
#pragma unroll
    for (int j = threadIdx.y; j < 32; j += 8)
        t[j][threadIdx.x] = in[(size_t)(by + j) * C + bx + threadIdx.x];
    __syncthreads();
#pragma unroll
    for (int j = threadIdx.y; j < 32; j += 8)
        outp[(size_t)(bx + j) * R + by + threadIdx.x] = __float2half_rn(t[threadIdx.x][j]);
}

// ---------------------------------------------------------------------------
// fp16 tensor-core GEMM: C[M,N] = A[M,K] * Bt[N,K]^T + bias[N]
// A, Bt: f16 K-major. 128x128 tile, BK=64 double-buffered cp.async.
// 8 warps (2x4), warp tile 64x32, m16n8k16. ldmatrix fragments. 2 CTAs/SM.
// Output: f32 (Cf) or f16 (Ch) selected by store_half.
// ---------------------------------------------------------------------------
#define GT   256
#define GBM  128
#define GBN  128
#define GBK  64
#define LDH  72                      // halves per smem row (144B, 16B-aligned, conflict-free)
#define GA_H (GBM * LDH)             // 9216 halves
#define GB_H (GBN * LDH)
#define G_SMEM_BYTES (2 * (GA_H + GB_H) * 2)   // 73728

__global__ void __launch_bounds__(GT, 2)
gemm_f16(int M, int N, int K,
         const __half* __restrict__ A,
         const __half* __restrict__ Bt,
         const float* __restrict__ bias,
         float* __restrict__ Cf, __half* __restrict__ Ch, int store_half)
{
    extern __shared__ __half gsm[];
    const uint32_t sA_u = smem_u32(gsm);
    const uint32_t sB_u = sA_u + 2 * GA_H * 2;   // after both A stages

    const int tid  = threadIdx.x;
    const int wid  = tid >> 5;
    const int lane = tid & 31;
    const int lq   = lane >> 2;
    const int lr   = lane & 3;
    const int wm   = wid & 1;
    const int wn   = wid >> 1;

    const size_t row0 = (size_t)blockIdx.y * GBM;
    const size_t col0 = (size_t)blockIdx.x * GBN;
    const int NC = K / GBK;

    const int lrow = tid >> 3;        // 0..31 (x4 via it)
    const int lch  = (tid & 7) * 8;   // half offset within row

    auto issue = [&](int kc, int buf) {
        const __half* Ag = A  + row0 * K + (size_t)kc * GBK;
        const __half* Bg = Bt + col0 * K + (size_t)kc * GBK;
        uint32_t dA = sA_u + (uint32_t)(buf * GA_H) * 2;
        uint32_t dB = sB_u + (uint32_t)(buf * GB_H) * 2;
#pragma unroll
        for (int it = 0; it < 4; ++it) {
            int r = lrow + it * 32;
            CP_ASYNC16(dA + (uint32_t)(r * LDH + lch) * 2, Ag + (size_t)r * K + lch);
            CP_ASYNC16(dB + (uint32_t)(r * LDH + lch) * 2, Bg + (size_t)r * K + lch);
        }
        CP_COMMIT();
    };

    float acc[4][4][4];
#pragma unroll
    for (int mi = 0; mi < 4; ++mi)
#pragma unroll
        for (int ni = 0; ni < 4; ++ni)
#pragma unroll
            for (int j = 0; j < 4; ++j) acc[mi][ni][j] = 0.0f;

    // ldmatrix lane address offsets (bytes) within a stage
    const uint32_t aOff = (uint32_t)((wm * 64 + (lane & 15)) * LDH + (lane >> 4) * 8) * 2;
    const uint32_t bOff = (uint32_t)((wn * 32 + (lane & 7) + ((lane >> 4) & 1) * 8) * LDH
                                     + ((lane >> 3) & 1) * 8) * 2;

    issue(0, 0);

    for (int kc = 0; kc < NC; ++kc) {
        if (kc + 1 < NC) { issue(kc + 1, (kc + 1) & 1); CP_WAIT1(); }
        else             { CP_WAIT0(); }
        __syncthreads();

        const uint32_t aS = sA_u + (uint32_t)((kc & 1) * GA_H) * 2 + aOff;
        const uint32_t bS = sB_u + (uint32_t)((kc & 1) * GB_H) * 2 + bOff;
#pragma unroll
        for (int kk = 0; kk < 4; ++kk) {
            uint32_t a[4][4], b[4][2];
#pragma unroll
            for (int mi = 0; mi < 4; ++mi)
                LDM_X4(a[mi][0], a[mi][1], a[mi][2], a[mi][3],
                       aS + (uint32_t)(mi * 16 * LDH) * 2 + kk * 32);
#pragma unroll
            for (int p = 0; p < 2; ++p)
                LDM_X4(b[2 * p][0], b[2 * p][1], b[2 * p + 1][0], b[2 * p + 1][1],
                       bS + (uint32_t)(p * 16 * LDH) * 2 + kk * 32);
#pragma unroll
            for (int mi = 0; mi < 4; ++mi)
#pragma unroll
                for (int ni = 0; ni < 4; ++ni)
                    MMA_F16(acc[mi][ni], a[mi], b[ni]);
        }
        __syncthreads();
    }

    // Epilogue
#pragma unroll
    for (int mi = 0; mi < 4; ++mi) {
#pragma unroll
        for (int ni = 0; ni < 4; ++ni) {
            size_t r  = row0 + wm * 64 + mi * 16 + lq;
            size_t cn = col0 + wn * 32 + ni * 8 + 2 * lr;
            float2 bv = *(const float2*)(bias + cn);
            float v00 = acc[mi][ni][0] + bv.x, v01 = acc[mi][ni][1] + bv.y;
            float v10 = acc[mi][ni][2] + bv.x, v11 = acc[mi][ni][3] + bv.y;
            if (store_half) {
                *(uint32_t*)(Ch + r * N + cn)       = packh2(v00, v01);
                *(uint32_t*)(Ch + (r + 8) * N + cn) = packh2(v10, v11);
            } else {
                *(float2*)(Cf + r * N + cn)       = make_float2(v00, v01);
                *(float2*)(Cf + (r + 8) * N + cn) = make_float2(v10, v11);
            }
        }
    }
}

// ---------------------------------------------------------------------------
// fp16 flash attention. 128 q-rows per CTA (8 warps x 16 rows), KV tiles of 64,
// double-buffered via cp.async. S C-frags repacked directly as PV A-frags.
// ---------------------------------------------------------------------------
#define AQ    128
#define AKV   64
#define AT_NT (T_SEQ / AKV)
#define Q_H   (AQ * LDH)             // 9216 halves
#define KV_H  (AKV * LDH)            // 4608 halves per stage
#define ATT_SMEM_BYTES ((Q_H + 4 * KV_H) * 2)   // 55296

__global__ void __launch_bounds__(256, 2)
flash_attn_f16(const __half* __restrict__ qkv, __half* __restrict__ outp)
{
    extern __shared__ __half hsm[];
    const uint32_t sQ_u = smem_u32(hsm);
    const uint32_t sK_u = sQ_u + Q_H * 2;            // 2 stages
    const uint32_t sV_u = sK_u + 2 * KV_H * 2;       // 2 stages

    const int tid  = threadIdx.x;
    const int wid  = tid >> 5;
    const int lane = tid & 31;
    const int lq   = lane >> 2;
    const int lr   = lane & 3;

    const int bh = blockIdx.y;
    const int b  = bh >> 4;
    const int h  = bh & 15;
    const int q0 = blockIdx.x * AQ;

    const __half* qb = qkv + ((size_t)b * T_SEQ) * (3 * D_MODEL) + h * H_DIM;
    const __half* kb = qb + D_MODEL;
    const __half* vb = qb + 2 * D_MODEL;

    const int lrow = tid >> 3;
    const int lch  = (tid & 7) * 8;

    // Q tile: 128 rows x 8 chunks
    {
#pragma unroll
        for (int it = 0; it < 4; ++it) {
            int r = lrow + it * 32;
            CP_ASYNC16(sQ_u + (uint32_t)(r * LDH + lch) * 2,
                       qb + (size_t)(q0 + r) * (3 * D_MODEL) + lch);
        }
    }
    auto issue_kv = [&](int kt, int buf) {
        int k0 = kt * AKV;
        uint32_t dK = sK_u + (uint32_t)(buf * KV_H) * 2;
        uint32_t dV = sV_u + (uint32_t)(buf * KV_H) * 2;
#pragma unroll
        for (int it = 0; it < 2; ++it) {
            int r = lrow + it * 32;
            CP_ASYNC16(dK + (uint32_t)(r * LDH + lch) * 2,
                       kb + (size_t)(k0 + r) * (3 * D_MODEL) + lch);
            CP_ASYNC16(dV + (uint32_t)(r * LDH + lch) * 2,
                       vb + (size_t)(k0 + r) * (3 * D_MODEL) + lch);
        }
    };
    issue_kv(0, 0);
    CP_COMMIT();            // G0: Q + KV0
    issue_kv(1, 1);
    CP_COMMIT();            // G1: KV1

    float o[8][4];
    float m0 = -INFINITY, m1 = -INFINITY, l0 = 0.0f, l1 = 0.0f;
#pragma unroll
    for (int ni = 0; ni < 8; ++ni)
#pragma unroll
        for (int j = 0; j < 4; ++j) o[ni][j] = 0.0f;

    const float scale = 0.125f;
    uint32_t qfrag[4][4];

    // ldmatrix lane offsets (bytes)
    const uint32_t qOff = (uint32_t)((wid * 16 + (lane & 15)) * LDH + (lane >> 4) * 8) * 2;
    const uint32_t kOff = (uint32_t)(((lane & 7) + ((lane >> 4) & 1) * 8) * LDH
                                     + ((lane >> 3) & 1) * 8) * 2;
    const uint32_t vOff = (uint32_t)(((lane & 7) + ((lane >> 3) & 1) * 8) * LDH
                                     + (lane >> 4) * 8) * 2;

    for (int kt = 0; kt < AT_NT; ++kt) {
        if (kt + 1 < AT_NT) CP_WAIT1(); else CP_WAIT0();
        __syncthreads();

        if (kt == 0) {
#pragma unroll
            for (int kk = 0; kk < 4; ++kk)
                LDM_X4(qfrag[kk][0], qfrag[kk][1], qfrag[kk][2], qfrag[kk][3],
                       sQ_u + qOff + kk * 32);
        }

        const uint32_t kS = sK_u + (uint32_t)((kt & 1) * KV_H) * 2 + kOff;
        const uint32_t vS = sV_u + (uint32_t)((kt & 1) * KV_H) * 2 + vOff;

        // S = Q K^T  (16 x 64 per warp)
        float c[8][4];
#pragma unroll
        for (int ni = 0; ni < 8; ++ni)
#pragma unroll
            for (int j = 0; j < 4; ++j) c[ni][j] = 0.0f;

#pragma unroll
        for (int kk = 0; kk < 4; ++kk) {
            uint32_t bfr[8][2];
#pragma unroll
            for (int p = 0; p < 4; ++p)
                LDM_X4(bfr[2 * p][0], bfr[2 * p][1], bfr[2 * p + 1][0], bfr[2 * p + 1][1],
                       kS + (uint32_t)(p * 16 * LDH) * 2 + kk * 32);
#pragma unroll
            for (int ni = 0; ni < 8; ++ni)
                MMA_F16(c[ni], qfrag[kk], bfr[ni]);
        }

        // Online softmax (rows lq via c[.][0,1], lq+8 via c[.][2,3])
        float rm0 = -INFINITY, rm1 = -INFINITY;
#pragma unroll
        for (int ni = 0; ni < 8; ++ni) {
#pragma unroll
            for (int j = 0; j < 4; ++j) c[ni][j] *= scale;
            rm0 = fmaxf(rm0, fmaxf(c[ni][0], c[ni][1]));
            rm1 = fmaxf(rm1, fmaxf(c[ni][2], c[ni][3]));
        }
        rm0 = fmaxf(rm0, __shfl_xor_sync(0xffffffffu, rm0, 1));
        rm0 = fmaxf(rm0, __shfl_xor_sync(0xffffffffu, rm0, 2));
        rm1 = fmaxf(rm1, __shfl_xor_sync(0xffffffffu, rm1, 1));
        rm1 = fmaxf(rm1, __shfl_xor_sync(0xffffffffu, rm1, 2));

        float mn0 = fmaxf(m0, rm0), mn1 = fmaxf(m1, rm1);
        float al0 = __expf(m0 - mn0), al1 = __expf(m1 - mn1);
        m0 = mn0; m1 = mn1;

        float rs0 = 0.0f, rs1 = 0.0f;
#pragma unroll
        for (int ni = 0; ni < 8; ++ni) {
            c[ni][0] = __expf(c[ni][0] - mn0);
            c[ni][1] = __expf(c[ni][1] - mn0);
            c[ni][2] = __expf(c[ni][2] - mn1);
            c[ni][3] = __expf(c[ni][3] - mn1);
            rs0 += c[ni][0] + c[ni][1];
            rs1 += c[ni][2] + c[ni][3];
        }
        rs0 += __shfl_xor_sync(0xffffffffu, rs0, 1);
        rs0 += __shfl_xor_sync(0xffffffffu, rs0, 2);
        rs1 += __shfl_xor_sync(0xffffffffu, rs1, 1);
        rs1 += __shfl_xor_sync(0xffffffffu, rs1, 2);

        l0 = l0 * al0 + rs0;
        l1 = l1 * al1 + rs1;
#pragma unroll
        for (int ni = 0; ni < 8; ++ni) {
            o[ni][0] *= al0; o[ni][1] *= al0;
            o[ni][2] *= al1; o[ni][3] *= al1;
        }

        // O += P @ V : P fragments packed directly from S C-frags
#pragma unroll
        for (int j = 0; j < 4; ++j) {
            uint32_t a[4];
            a[0] = packh2(c[2 * j][0],     c[2 * j][1]);
            a[1] = packh2(c[2 * j][2],     c[2 * j][3]);
            a[2] = packh2(c[2 * j + 1][0], c[2 * j + 1][1]);
            a[3] = packh2(c[2 * j + 1][2], c[2 * j + 1][3]);
            uint32_t bfr[8][2];
#pragma unroll
            for (int p = 0; p < 4; ++p)
                LDM_X4_T(bfr[2 * p][0], bfr[2 * p][1], bfr[2 * p + 1][0], bfr[2 * p + 1][1],
                         vS + (uint32_t)(j * 16 * LDH) * 2 + p * 32);
#pragma unroll
            for (int ni = 0; ni < 8; ++ni)
                MMA_F16(o[ni], a, bfr[ni]);
        }

        __syncthreads();
        if (kt + 2 < AT_NT) { issue_kv(kt + 2, kt & 1); CP_COMMIT(); }
    }

    // Normalize + write f16
    float inv0 = 1.0f / l0, inv1 = 1.0f / l1;
    size_t row_g = (size_t)b * T_SEQ + q0 + wid * 16 + lq;
#pragma unroll
    for (int ni = 0; ni < 8; ++ni) {
        int cn = h * H_DIM + ni * 8 + 2 * lr;
        *(uint32_t*)(outp + row_g * D_MODEL + cn) =
            packh2(o[ni][0] * inv0, o[ni][1] * inv0);
        *(uint32_t*)(outp + (row_g + 8) * D_MODEL + cn) =
            packh2(o[ni][2] * inv1, o[ni][3] * inv1);
    }
}

// ---------------------------------------------------------------------------
extern "C" void kernel_launch(void* const* d_in, const int* in_sizes, int n_in,
                              void* d_out, int out_size)
{
    const float* x     = (const float*)d_in[0];
    const float* W_qkv = (const float*)d_in[1];
    const float* b_qkv = (const float*)d_in[2];
    const float* W_out = (const float*)d_in[3];
    const float* b_out = (const float*)d_in[4];
    float*       out   = (float*)d_out;

    __half *x_h, *wqkv_t, *wout_t, *qkv_h, *att_h;
    cudaGetSymbolAddress((void**)&x_h,    g_x_h);
    cudaGetSymbolAddress((void**)&wqkv_t, g_wqkv_t);
    cudaGetSymbolAddress((void**)&wout_t, g_wout_t);
    cudaGetSymbolAddress((void**)&qkv_h,  g_qkv_h);
    cudaGetSymbolAddress((void**)&att_h,  g_att_h);

    cudaFuncSetAttribute(gemm_f16,
                         cudaFuncAttributeMaxDynamicSharedMemorySize, G_SMEM_BYTES);
    cudaFuncSetAttribute(flash_attn_f16,
                         cudaFuncAttributeMaxDynamicSharedMemorySize, ATT_SMEM_BYTES);

    // 0) Conversions: x -> f16; W -> W^T f16
    {
        int n4 = (M_ROWS * D_MODEL) / 4;
        conv_f16_kernel<<<(n4 + 255) / 256, 256>>>(x, x_h, n4);
        dim3 blk(32, 8);
        conv_transpose_f16<<<dim3((3 * D_MODEL) / 32, D_MODEL / 32), blk>>>(
            W_qkv, wqkv_t, D_MODEL, 3 * D_MODEL);
        conv_transpose_f16<<<dim3(D_MODEL / 32, D_MODEL / 32), blk>>>(
            W_out, wout_t, D_MODEL, D_MODEL);
    }

    // 1) QKV projection -> f16 qkv
    {
        dim3 grid((3 * D_MODEL) / GBN, M_ROWS / GBM);
        gemm_f16<<<grid, GT, G_SMEM_BYTES>>>(
            M_ROWS, 3 * D_MODEL, D_MODEL, x_h, wqkv_t, b_qkv, nullptr, qkv_h, 1);
    }

    // 2) Attention -> f16 att
    {
        dim3 grid(T_SEQ / AQ, B_SIZE * N_HEADS);
        flash_attn_f16<<<grid, 256, ATT_SMEM_BYTES>>>(qkv_h, att_h);
    }

    // 3) Output projection -> f32 out
    {
        dim3 grid(D_MODEL / GBN, M_ROWS / GBM);
        gemm_f16<<<grid, GT, G_SMEM_BYTES>>>(
            M_ROWS, D_MODEL, D_MODEL, att_h, wout_t, b_out, out, nullptr, 0);
    }
}